// round 2
// baseline (speedup 1.0000x reference)
#include <cuda_runtime.h>
#include <cuda_bf16.h>
#include <cstdint>

// Problem shape (fixed by the dataset)
#define BB 64
#define CC 256
#define HH 80
#define WW 80
#define NN 100
#define IMG 640.0f

#define PLANE_ELEMS (HH * WW)          // 6400 floats
#define PLANE_BYTES (PLANE_ELEMS * 4)  // 25600 bytes

__device__ __forceinline__ uint32_t smem_u32(const void* p) {
    uint32_t a;
    asm("{ .reg .u64 t; cvta.to.shared.u64 t, %1; cvt.u32.u64 %0, t; }"
        : "=r"(a) : "l"(p));
    return a;
}

__device__ __forceinline__ void mbar_init(uint32_t mbar, uint32_t count) {
    asm volatile("mbarrier.init.shared.b64 [%0], %1;" :: "r"(mbar), "r"(count) : "memory");
}

__device__ __forceinline__ void mbar_expect_tx(uint32_t mbar, uint32_t bytes) {
    asm volatile("mbarrier.arrive.expect_tx.shared.b64 _, [%0], %1;"
                 :: "r"(mbar), "r"(bytes) : "memory");
}

__device__ __forceinline__ void bulk_copy_g2s(uint32_t dst_smem, const void* src_gmem,
                                              uint32_t bytes, uint32_t mbar) {
    asm volatile(
        "cp.async.bulk.shared::cta.global.mbarrier::complete_tx::bytes "
        "[%0], [%1], %2, [%3];"
        :: "r"(dst_smem), "l"(src_gmem), "r"(bytes), "r"(mbar) : "memory");
}

__device__ __forceinline__ void mbar_wait_parity(uint32_t mbar, uint32_t parity) {
    asm volatile(
        "{\n\t"
        ".reg .pred P1;\n\t"
        "WAIT_LOOP_%=:\n\t"
        "mbarrier.try_wait.parity.acquire.cta.shared::cta.b64 P1, [%0], %1, 0x989680;\n\t"
        "@P1 bra.uni WAIT_DONE_%=;\n\t"
        "bra.uni WAIT_LOOP_%=;\n\t"
        "WAIT_DONE_%=:\n\t"
        "}"
        :: "r"(mbar), "r"(parity) : "memory");
}

__global__ __launch_bounds__(128, 8)
void roi_pool_kernel(const float* __restrict__ fmap,
                     const float* __restrict__ boxes,
                     float* __restrict__ out)
{
    // Raw plane staged by TMA bulk copy (contiguous [80][80]), scanned in place.
    __shared__ __align__(128) float S[PLANE_ELEMS];   // 25.6 KB
    __shared__ __align__(8) uint64_t mbar_storage;

    const int c = blockIdx.x;   // channel
    const int b = blockIdx.y;   // batch
    const int t = threadIdx.x;  // 128 threads

    const float* plane = fmap + ((size_t)(b * CC + c)) * PLANE_ELEMS;
    const uint32_t s_base = smem_u32(S);
    const uint32_t mbar = smem_u32(&mbar_storage);

    // ---- Async bulk load of the whole plane (one DMA, no per-lane LDG latency).
    if (t == 0) {
        mbar_init(mbar, 1);
        // Make the init visible to the async proxy before the TMA write lands.
        asm volatile("fence.proxy.async.shared::cta;" ::: "memory");
        mbar_expect_tx(mbar, PLANE_BYTES);
        bulk_copy_g2s(s_base, plane, PLANE_BYTES, mbar);
    }
    __syncthreads();          // all threads see initialized barrier
    mbar_wait_parity(mbar, 0);  // data resident in S

    // ---- Pass 1: cumulative sum over y (axis=2), in place.
    // Thread t owns column t: addr t + 80*y. At fixed y, lanes hit
    // consecutive banks -> conflict-free.
    if (t < WW) {
        float acc = 0.0f;
        #pragma unroll
        for (int y = 0; y < HH; ++y) {
            float v = S[y * WW + t];
            acc += v;
            S[y * WW + t] = acc;
        }
    }
    __syncthreads();

    // ---- Pass 2: cumulative sum over x (axis=3), per row, float4, in place.
    // S becomes the INCLUSIVE integral image.
    if (t < HH) {
        float* row = S + t * WW;
        float acc = 0.0f;
        #pragma unroll
        for (int g = 0; g < WW / 4; ++g) {
            float4 v = *reinterpret_cast<float4*>(row + 4 * g);
            v.x += acc;
            v.y += v.x;
            v.z += v.y;
            v.w += v.z;
            acc = v.w;
            *reinterpret_cast<float4*>(row + 4 * g) = v;
        }
    }
    __syncthreads();

    // ---- Pass 3: evaluate all 100 boxes of batch b for this channel.
    if (t < NN) {
        float4 bx = reinterpret_cast<const float4*>(boxes)[b * NN + t];

        // Exactly reference math: (coord / 640) * 80 in fp32 RN, then int
        // truncation (non-negative => floor), clip into [0, dim].
        int x1 = (int)__fmul_rn(__fdiv_rn(bx.x, IMG), (float)WW);
        int y1 = (int)__fmul_rn(__fdiv_rn(bx.y, IMG), (float)HH);
        int x2 = (int)__fmul_rn(__fdiv_rn(bx.z, IMG), (float)WW);
        int y2 = (int)__fmul_rn(__fdiv_rn(bx.w, IMG), (float)HH);
        x1 = min(max(x1, 0), WW);
        y1 = min(max(y1, 0), HH);
        x2 = min(max(x2, 0), WW);
        y2 = min(max(y2, 0), HH);

        const int dy = y2 - y1;
        const int dx = x2 - x1;

        float r = 0.0f;
        if (dy > 0 && dx > 0) {
            // Inclusive integral -> exclusive corners at (y-1, x-1); border = 0.
            float s22 = S[(y2 - 1) * WW + (x2 - 1)];
            float s12 = (y1 > 0) ? S[(y1 - 1) * WW + (x2 - 1)] : 0.0f;
            float s21 = (x1 > 0) ? S[(y2 - 1) * WW + (x1 - 1)] : 0.0f;
            float s11 = (y1 > 0 && x1 > 0) ? S[(y1 - 1) * WW + (x1 - 1)] : 0.0f;
            float ssum = s22 - s12 - s21 + s11;
            r = __fdiv_rn(ssum, (float)(dy * dx));
        }
        // out[b, n, c]; output (6.5 MB) fits in L2, scattered 4B stores merge.
        out[((size_t)b * NN + t) * CC + c] = r;
    }
}

extern "C" void kernel_launch(void* const* d_in, const int* in_sizes, int n_in,
                              void* d_out, int out_size)
{
    const float* fmap  = (const float*)d_in[0];   // [64,256,80,80]
    const float* boxes = (const float*)d_in[1];   // [64,100,4]
    float* out = (float*)d_out;                   // [64,100,256]

    dim3 grid(CC, BB);   // one CTA per (b, c) plane
    dim3 block(128);
    roi_pool_kernel<<<grid, block>>>(fmap, boxes, out);
}

// round 3
// speedup vs baseline: 1.3302x; 1.3302x over previous
#include <cuda_runtime.h>
#include <cuda_bf16.h>
#include <cstdint>

// Problem shape (fixed by the dataset)
#define BB 64
#define CC 256
#define HH 80
#define WW 80
#define NN 100
#define IMG 640.0f

#define NPLANES (BB * CC)          // 16384 planes of 80x80 floats
#define PLANE_ELEMS (HH * WW)      // 6400
#define PLANE_F4 (PLANE_ELEMS / 4) // 1600 16B chunks per plane
#define PSTRIDE 84                 // padded smem row stride (floats); 84%4==0
#define PBUF (HH * PSTRIDE)        // floats per buffer (6720)
#define GRID 608                   // 152 SMs * 4 resident CTAs
#define THREADS 128

__device__ __forceinline__ uint32_t smem_u32(const void* p) {
    uint32_t a;
    asm("{ .reg .u64 t; cvta.to.shared.u64 t, %1; cvt.u32.u64 %0, t; }"
        : "=r"(a) : "l"(p));
    return a;
}

__device__ __forceinline__ void cp_async16(uint32_t dst, const void* src) {
    asm volatile("cp.async.cg.shared.global [%0], [%1], 16;"
                 :: "r"(dst), "l"(src) : "memory");
}
__device__ __forceinline__ void cp_commit() {
    asm volatile("cp.async.commit_group;" ::: "memory");
}
template <int N>
__device__ __forceinline__ void cp_wait() {
    asm volatile("cp.async.wait_group %0;" :: "n"(N) : "memory");
}

// Issue async copy of one full plane into padded smem buffer.
// Chunk j (16B) holds row j/20, cols [4*(j%20), 4*(j%20)+4) -> padded float4
// slot row*21 + (j%20). All 128 threads participate (13 rounds, last partial).
__device__ __forceinline__ void prefetch_plane(const float* __restrict__ plane,
                                               uint32_t dbase, int t) {
    #pragma unroll
    for (int k = 0; k < 13; ++k) {
        int j = t + k * THREADS;
        if (j < PLANE_F4) {
            int row  = j / 20;
            int col4 = j % 20;
            uint32_t dst = dbase + (uint32_t)(row * 21 + col4) * 16u;
            cp_async16(dst, plane + j * 4);
        }
    }
}

__global__ __launch_bounds__(THREADS, 4)
void roi_pool_kernel(const float* __restrict__ fmap,
                     const float* __restrict__ boxes,
                     float* __restrict__ out)
{
    extern __shared__ __align__(16) float P[];   // [2][PBUF]
    const int t = threadIdx.x;
    const uint32_t pbase = smem_u32(P);

    int p = blockIdx.x;           // plane for iteration 0 (grid-stride)
    if (p < NPLANES) {
        prefetch_plane(fmap + (size_t)p * PLANE_ELEMS, pbase, t);
        cp_commit();
    }

    int i = 0;
    for (; p < NPLANES; p += GRID, ++i) {
        const int buf = i & 1;
        const int pn = p + GRID;

        // Prefetch next plane into the other buffer (consumed 2 iters ago,
        // protected by the trailing __syncthreads of the previous iteration).
        if (pn < NPLANES) {
            prefetch_plane(fmap + (size_t)pn * PLANE_ELEMS,
                           pbase + (uint32_t)((buf ^ 1) * PBUF) * 4u, t);
            cp_commit();
            cp_wait<1>();     // current plane's group complete
        } else {
            cp_wait<0>();
        }
        __syncthreads();      // current buffer visible to all threads

        float* S = P + buf * PBUF;

        // ---- Pass 1: cumsum over y (axis=2), in place. Thread t owns column
        // t; at fixed y, lanes hit consecutive banks -> conflict-free.
        if (t < WW) {
            float acc = 0.0f;
            #pragma unroll 16
            for (int y = 0; y < HH; ++y) {
                acc += S[y * PSTRIDE + t];
                S[y * PSTRIDE + t] = acc;
            }
        }
        __syncthreads();

        // ---- Pass 2: cumsum over x (axis=3), per row, float4, in place.
        // Stride 21 float4 per row -> benign bank phasing (proven in R1).
        if (t < HH) {
            float4* row = reinterpret_cast<float4*>(S + t * PSTRIDE);
            float acc = 0.0f;
            #pragma unroll
            for (int g = 0; g < WW / 4; ++g) {
                float4 v = row[g];
                v.x += acc;
                v.y += v.x;
                v.z += v.y;
                v.w += v.z;
                acc = v.w;
                row[g] = v;
            }
        }
        __syncthreads();

        // ---- Pass 3: evaluate the 100 boxes of this plane's batch.
        if (t < NN) {
            const int b = p / CC;     // planes ordered [B][C]
            const int c = p % CC;
            float4 bx = reinterpret_cast<const float4*>(boxes)[b * NN + t];

            // Reference math exactly: (coord/640)*80 in fp32 RN, int
            // truncation (non-negative => floor), clip into [0, dim].
            int x1 = (int)__fmul_rn(__fdiv_rn(bx.x, IMG), (float)WW);
            int y1 = (int)__fmul_rn(__fdiv_rn(bx.y, IMG), (float)HH);
            int x2 = (int)__fmul_rn(__fdiv_rn(bx.z, IMG), (float)WW);
            int y2 = (int)__fmul_rn(__fdiv_rn(bx.w, IMG), (float)HH);
            x1 = min(max(x1, 0), WW);
            y1 = min(max(y1, 0), HH);
            x2 = min(max(x2, 0), WW);
            y2 = min(max(y2, 0), HH);

            const int dy = y2 - y1;
            const int dx = x2 - x1;

            float r = 0.0f;
            if (dy > 0 && dx > 0) {
                // Inclusive integral -> exclusive corners at (y-1,x-1); border 0.
                float s22 = S[(y2 - 1) * PSTRIDE + (x2 - 1)];
                float s12 = (y1 > 0) ? S[(y1 - 1) * PSTRIDE + (x2 - 1)] : 0.0f;
                float s21 = (x1 > 0) ? S[(y2 - 1) * PSTRIDE + (x1 - 1)] : 0.0f;
                float s11 = (y1 > 0 && x1 > 0) ? S[(y1 - 1) * PSTRIDE + (x1 - 1)] : 0.0f;
                r = __fdiv_rn(s22 - s12 - s21 + s11, (float)(dy * dx));
            }
            out[((size_t)b * NN + t) * CC + c] = r;
        }

        // All reads of buf done before next iteration's prefetch overwrites
        // the opposite buffer... and before iteration i+1 refills THIS buffer
        // two steps from now; also orders pass-3 smem reads vs refill of buf^1.
        __syncthreads();
    }
}

extern "C" void kernel_launch(void* const* d_in, const int* in_sizes, int n_in,
                              void* d_out, int out_size)
{
    const float* fmap  = (const float*)d_in[0];   // [64,256,80,80]
    const float* boxes = (const float*)d_in[1];   // [64,100,4]
    float* out = (float*)d_out;                   // [64,100,256]

    const int smem_bytes = 2 * PBUF * sizeof(float);   // 53760
    cudaFuncSetAttribute(roi_pool_kernel,
                         cudaFuncAttributeMaxDynamicSharedMemorySize,
                         smem_bytes);

    roi_pool_kernel<<<GRID, THREADS, smem_bytes>>>(fmap, boxes, out);
}

// round 4
// speedup vs baseline: 1.4767x; 1.1102x over previous
#include <cuda_runtime.h>
#include <cuda_bf16.h>
#include <cstdint>

// Problem shape (fixed by the dataset)
#define BB 64
#define CC 256
#define HH 80
#define WW 80
#define NN 100
#define IMG 640.0f

#define NPLANES (BB * CC)          // 16384 planes of 80x80 floats
#define PLANE_ELEMS (HH * WW)      // 6400
#define PLANE_F4 (PLANE_ELEMS / 4) // 1600 16B chunks per plane
#define PSTRIDE 84                 // padded smem row stride (floats)
#define PBUF (HH * PSTRIDE)        // floats per slot (6720 = 26.88 KB)
#define NSLOTS 8                   // ring slots (2 per consumer group)
#define NGROUPS 4                  // consumer groups of 3 warps (96 lanes)
#define GRID 152                   // persistent: one CTA per SM
#define TPB 416                    // 12 consumer warps + 1 producer warp

__device__ __forceinline__ uint32_t smem_u32(const void* p) {
    uint32_t a;
    asm("{ .reg .u64 t; cvta.to.shared.u64 t, %1; cvt.u32.u64 %0, t; }"
        : "=r"(a) : "l"(p));
    return a;
}

__device__ __forceinline__ void cp_async16(uint32_t dst, const void* src) {
    asm volatile("cp.async.cg.shared.global [%0], [%1], 16;"
                 :: "r"(dst), "l"(src) : "memory");
}

__device__ __forceinline__ void mbar_init(uint32_t mbar, uint32_t count) {
    asm volatile("mbarrier.init.shared.b64 [%0], %1;"
                 :: "r"(mbar), "r"(count) : "memory");
}

__device__ __forceinline__ void mbar_arrive(uint32_t mbar) {
    asm volatile("mbarrier.arrive.shared.b64 _, [%0];" :: "r"(mbar) : "memory");
}

// Arrive on mbar once all prior cp.asyncs of this thread have completed.
// .noinc: counts toward the barrier's init expected count.
__device__ __forceinline__ void cpasync_mbar_arrive(uint32_t mbar) {
    asm volatile("cp.async.mbarrier.arrive.noinc.shared::cta.b64 [%0];"
                 :: "r"(mbar) : "memory");
}

__device__ __forceinline__ void mbar_wait_parity(uint32_t mbar, uint32_t parity) {
    asm volatile(
        "{\n\t"
        ".reg .pred P1;\n\t"
        "WAIT_LOOP_%=:\n\t"
        "mbarrier.try_wait.parity.acquire.cta.shared::cta.b64 P1, [%0], %1, 0x989680;\n\t"
        "@P1 bra.uni WAIT_DONE_%=;\n\t"
        "bra.uni WAIT_LOOP_%=;\n\t"
        "WAIT_DONE_%=:\n\t"
        "}"
        :: "r"(mbar), "r"(parity) : "memory");
}

__device__ __forceinline__ void named_bar(int id, int count) {
    asm volatile("bar.sync %0, %1;" :: "r"(id), "r"(count) : "memory");
}

__global__ __launch_bounds__(TPB, 1)
void roi_pool_kernel(const float* __restrict__ fmap,
                     const float* __restrict__ boxes,
                     float* __restrict__ out)
{
    extern __shared__ __align__(16) float P[];   // [NSLOTS][PBUF] = 215 KB
    __shared__ __align__(8) uint64_t full_bar[NSLOTS];
    __shared__ __align__(8) uint64_t empty_bar[NSLOTS];

    const int tid  = threadIdx.x;
    const int wid  = tid >> 5;
    const int lane = tid & 31;
    const int bid  = blockIdx.x;
    const uint32_t pbase = smem_u32(P);

    if (tid == 0) {
        #pragma unroll
        for (int s = 0; s < NSLOTS; ++s) {
            mbar_init(smem_u32(&full_bar[s]), 32);  // 32 producer-lane arrivals
            mbar_init(smem_u32(&empty_bar[s]), 1);  // 1 consumer arrival
        }
        asm volatile("fence.proxy.async.shared::cta;" ::: "memory");
    }
    __syncthreads();

    if (wid == 12) {
        // ================= PRODUCER WARP =================
        // CTA's j-th plane: p = bid + j*GRID. Slot = (j%4)*2 + ((j/4)&1).
        // Slot use counter u = j/8; phase u needs empty phase u-1 complete.
        for (int j = 0; ; ++j) {
            const int p = bid + j * GRID;
            if (p >= NPLANES) break;
            const int slot = ((j & 3) << 1) + ((j >> 2) & 1);
            const int u = j >> 3;
            if (u > 0)
                mbar_wait_parity(smem_u32(&empty_bar[slot]), (u - 1) & 1);

            const float* plane = fmap + (size_t)p * PLANE_ELEMS;
            const uint32_t sbase = pbase + (uint32_t)(slot * PBUF) * 4u;
            // 1600 16B chunks, lane-interleaved (warp instr = 512B contiguous),
            // scattered into the padded layout: chunk ch -> float4 slot
            // (ch/20)*21 + ch%20.
            #pragma unroll 5
            for (int k = 0; k < PLANE_F4 / 32; ++k) {
                const int ch  = lane + (k << 5);
                const int row = ch / 20;
                const int c4  = ch % 20;
                cp_async16(sbase + (uint32_t)(row * 21 + c4) * 16u,
                           plane + ch * 4);
            }
            cpasync_mbar_arrive(smem_u32(&full_bar[slot]));
        }
    } else {
        // ================= CONSUMER GROUPS =================
        const int g  = wid / 3;                 // group 0..3
        const int gt = (wid % 3) * 32 + lane;   // 0..95 within group
        const int barid = g + 1;                // named barrier ids 1..4

        for (int k = 0; ; ++k) {
            const int j = (k << 2) + g;         // this group's j-th assignment
            const int p = bid + j * GRID;
            if (p >= NPLANES) break;
            const int slot = (g << 1) + (k & 1);
            const int v = k >> 1;               // fill counter for this slot

            mbar_wait_parity(smem_u32(&full_bar[slot]), v & 1);
            float* S = P + slot * PBUF;

            // ---- Pass 1: cumsum over y. Thread gt owns column gt (gt<80).
            // Consecutive lanes -> consecutive banks: conflict-free.
            if (gt < WW) {
                float acc = 0.0f;
                #pragma unroll 16
                for (int y = 0; y < HH; ++y) {
                    acc += S[y * PSTRIDE + gt];
                    S[y * PSTRIDE + gt] = acc;
                }
            }
            named_bar(barid, 96);

            // ---- Pass 2: cumsum over x, per row, float4. Row stride 21
            // float4 -> distinct banks within each 8-lane phase.
            if (gt < HH) {
                float4* row = reinterpret_cast<float4*>(S + gt * PSTRIDE);
                float acc = 0.0f;
                #pragma unroll
                for (int q = 0; q < WW / 4; ++q) {
                    float4 v4 = row[q];
                    v4.x += acc;
                    v4.y += v4.x;
                    v4.z += v4.y;
                    v4.w += v4.z;
                    acc = v4.w;
                    row[q] = v4;
                }
            }
            named_bar(barid, 96);

            // ---- Pass 3: 100 boxes of batch p/CC (2 rounds over 96 lanes).
            const int b = p / CC;
            const int c = p % CC;
            #pragma unroll
            for (int r0 = 0; r0 < 2; ++r0) {
                const int n = gt + r0 * 96;
                if (n < NN) {
                    float4 bx = reinterpret_cast<const float4*>(boxes)[b * NN + n];
                    // Reference math exactly: (coord/640)*80 fp32 RN, int
                    // truncation (non-negative => floor), clip to [0, dim].
                    int x1 = (int)__fmul_rn(__fdiv_rn(bx.x, IMG), (float)WW);
                    int y1 = (int)__fmul_rn(__fdiv_rn(bx.y, IMG), (float)HH);
                    int x2 = (int)__fmul_rn(__fdiv_rn(bx.z, IMG), (float)WW);
                    int y2 = (int)__fmul_rn(__fdiv_rn(bx.w, IMG), (float)HH);
                    x1 = min(max(x1, 0), WW);
                    y1 = min(max(y1, 0), HH);
                    x2 = min(max(x2, 0), WW);
                    y2 = min(max(y2, 0), HH);

                    const int dy = y2 - y1;
                    const int dx = x2 - x1;
                    float r = 0.0f;
                    if (dy > 0 && dx > 0) {
                        // Inclusive integral -> exclusive corners; border 0.
                        float s22 = S[(y2 - 1) * PSTRIDE + (x2 - 1)];
                        float s12 = (y1 > 0) ? S[(y1 - 1) * PSTRIDE + (x2 - 1)] : 0.0f;
                        float s21 = (x1 > 0) ? S[(y2 - 1) * PSTRIDE + (x1 - 1)] : 0.0f;
                        float s11 = (y1 > 0 && x1 > 0) ? S[(y1 - 1) * PSTRIDE + (x1 - 1)] : 0.0f;
                        r = __fdiv_rn(s22 - s12 - s21 + s11, (float)(dy * dx));
                    }
                    out[((size_t)b * NN + n) * CC + c] = r;
                }
            }
            named_bar(barid, 96);   // all reads of S done
            if (gt == 0)
                mbar_arrive(smem_u32(&empty_bar[slot]));
        }
    }
}

extern "C" void kernel_launch(void* const* d_in, const int* in_sizes, int n_in,
                              void* d_out, int out_size)
{
    const float* fmap  = (const float*)d_in[0];   // [64,256,80,80]
    const float* boxes = (const float*)d_in[1];   // [64,100,4]
    float* out = (float*)d_out;                   // [64,100,256]

    const int smem_bytes = NSLOTS * PBUF * sizeof(float);   // 215040
    cudaFuncSetAttribute(roi_pool_kernel,
                         cudaFuncAttributeMaxDynamicSharedMemorySize,
                         smem_bytes);

    roi_pool_kernel<<<GRID, TPB, smem_bytes>>>(fmap, boxes, out);
}